// round 1
// baseline (speedup 1.0000x reference)
#include <cuda_runtime.h>
#include <math.h>

// ---------------- problem constants ----------------
#define Bc   2
#define Sc   1024
#define Hc   1024
#define Ic   2048
#define Nst  16
#define Rc   64
#define Kcv  4
#define NHc  16
#define NKVc 4
#define HDc  64
#define WATT 512
#define WSSM 128
#define IMc  2816
#define Mrows (Bc*Sc)        // 2048
#define EPSc  1e-6f
#define PROJW (Rc + 2*Nst)   // 96

// ---------------- scratch (static device globals; no allocation) ----------------
__device__ float g_hs[Mrows*Hc];
__device__ float g_xz[Mrows*2*Ic];
__device__ float g_xs[Mrows*Ic];
__device__ float g_proj[Mrows*PROJW];
__device__ float g_dt[Mrows*Ic];
__device__ float g_y[Mrows*Ic];
__device__ float g_tmp[Mrows*Hc];
__device__ float g_ssmres[Mrows*Hc];
__device__ float g_ssmst[Mrows*Hc];
__device__ float g_q[Mrows*NHc*HDc];
__device__ float g_katt[Mrows*NKVc*HDc];
__device__ float g_vatt[Mrows*NKVc*HDc];
__device__ float g_kssm[Mrows*NKVc*HDc];
__device__ float g_vssm[Mrows*NKVc*HDc];
__device__ float g_o[Mrows*NHc*HDc];
__device__ float g_mlpres[Mrows*Hc];
__device__ float g_x2[Mrows*Hc];
__device__ float g_gv[Mrows*2*IMc];
__device__ float g_hm[Mrows*IMc];

__device__ __forceinline__ float sigmoidf_(float x) { return 1.f / (1.f + expf(-x)); }

// ---------------- generic tiled SGEMM: C[m,n] = sum_k A[m,k]*B[n,k] ----------------
// A: (M x K) row-major with leading dim lda; B: (N x K) row-major with leading dim ldb.
// C row-major leading dim = Ndim. M must be multiple of 128, K multiple of 16. N guarded.
#define BM 128
#define BN 64
#define BK 16

__global__ __launch_bounds__(256, 2)
void gemm_nt(const float* __restrict__ A, const float* __restrict__ Bw,
             float* __restrict__ C, int Mdim, int Ndim, int Kdim, int lda, int ldb) {
    __shared__ float As[BK][BM + 4];
    __shared__ float Bs[BK][BN + 4];
    int t  = threadIdx.x;
    int bm = blockIdx.y * BM;
    int bn = blockIdx.x * BN;
    int rm = (t & 15) * 8;
    int cn = (t >> 4) * 4;

    float acc[8][4];
#pragma unroll
    for (int i = 0; i < 8; i++)
#pragma unroll
        for (int j = 0; j < 4; j++) acc[i][j] = 0.f;

    for (int k0 = 0; k0 < Kdim; k0 += BK) {
        // load A tile: 128x16 = 512 float4, 2 per thread
#pragma unroll
        for (int li = 0; li < 2; li++) {
            int id = t + li * 256;
            int r  = id >> 2;
            int kq = (id & 3) * 4;
            float4 v = *(const float4*)(A + (size_t)(bm + r) * lda + k0 + kq);
            As[kq + 0][r] = v.x; As[kq + 1][r] = v.y;
            As[kq + 2][r] = v.z; As[kq + 3][r] = v.w;
        }
        // load B tile: 64x16 = 256 float4, 1 per thread (row-guarded)
        {
            int r  = t >> 2;
            int kq = (t & 3) * 4;
            float4 v = make_float4(0.f, 0.f, 0.f, 0.f);
            if (bn + r < Ndim)
                v = *(const float4*)(Bw + (size_t)(bn + r) * ldb + k0 + kq);
            Bs[kq + 0][r] = v.x; Bs[kq + 1][r] = v.y;
            Bs[kq + 2][r] = v.z; Bs[kq + 3][r] = v.w;
        }
        __syncthreads();
#pragma unroll
        for (int kk = 0; kk < BK; kk++) {
            float a[8], b[4];
#pragma unroll
            for (int i = 0; i < 8; i++) a[i] = As[kk][rm + i];
#pragma unroll
            for (int j = 0; j < 4; j++) b[j] = Bs[kk][cn + j];
#pragma unroll
            for (int i = 0; i < 8; i++)
#pragma unroll
                for (int j = 0; j < 4; j++) acc[i][j] = fmaf(a[i], b[j], acc[i][j]);
        }
        __syncthreads();
    }
#pragma unroll
    for (int i = 0; i < 8; i++) {
        float* crow = C + (size_t)(bm + rm + i) * Ndim + bn + cn;
#pragma unroll
        for (int j = 0; j < 4; j++)
            if (bn + cn + j < Ndim) crow[j] = acc[i][j];
    }
}

// ---------------- RMSNorm (optional residual add) over 1024 cols ----------------
// x = a + (r ? r : 0); res_out (if non-null) <- x; nrm_out <- x * rsqrt(mean(x^2)+eps) * w
__global__ void resid_rms(const float* __restrict__ a, const float* __restrict__ r,
                          const float* __restrict__ w, float* __restrict__ res_out,
                          float* __restrict__ nrm_out) {
    int row = blockIdx.x;
    int t   = threadIdx.x;
    const float* ap = a + (size_t)row * Hc;
    const float* rp = r ? r + (size_t)row * Hc : nullptr;
    float v[4];
    float ss = 0.f;
#pragma unroll
    for (int i = 0; i < 4; i++) {
        int c = t + i * 256;
        float x = ap[c] + (rp ? rp[c] : 0.f);
        v[i] = x;
        ss += x * x;
    }
#pragma unroll
    for (int off = 16; off; off >>= 1) ss += __shfl_xor_sync(0xffffffffu, ss, off);
    __shared__ float sred[8];
    __shared__ float sscale;
    if ((t & 31) == 0) sred[t >> 5] = ss;
    __syncthreads();
    if (t == 0) {
        float tot = 0.f;
        for (int i = 0; i < 8; i++) tot += sred[i];
        sscale = rsqrtf(tot * (1.f / Hc) + EPSc);
    }
    __syncthreads();
    float scale = sscale;
    float* ro = res_out ? res_out + (size_t)row * Hc : nullptr;
    float* no = nrm_out + (size_t)row * Hc;
#pragma unroll
    for (int i = 0; i < 4; i++) {
        int c = t + i * 256;
        if (ro) ro[c] = v[i];
        no[c] = v[i] * scale * w[c];
    }
}

// ---------------- causal depthwise conv (K=4) + SiLU ----------------
__global__ void conv_silu(const float* __restrict__ cw, const float* __restrict__ cb) {
    int idx = blockIdx.x * blockDim.x + threadIdx.x;
    if (idx >= Mrows * Ic) return;
    int row = idx / Ic;
    int i   = idx - row * Ic;
    int b   = row / Sc;
    int s   = row - b * Sc;
    float acc = cb[i];
#pragma unroll
    for (int k = 0; k < Kcv; k++) {
        int sp = s + k - (Kcv - 1);
        if (sp >= 0)
            acc += cw[i * Kcv + k] * g_xz[(size_t)(b * Sc + sp) * (2 * Ic) + i];
    }
    g_xs[idx] = acc * sigmoidf_(acc);
}

// ---------------- dt bias + softplus (in place on g_dt) ----------------
__global__ void bias_softplus(const float* __restrict__ dtb) {
    int idx = blockIdx.x * blockDim.x + threadIdx.x;
    if (idx >= Mrows * Ic) return;
    int i = idx % Ic;
    float x = g_dt[idx] + dtb[i];
    g_dt[idx] = (x > 20.f) ? x : log1pf(expf(x));
}

// ---------------- selective scan ----------------
// 256 threads = 16 channels x 16 states. grid = B*I/16 = 256.
__global__ void scan_kernel(const float* __restrict__ A_log, const float* __restrict__ Dp) {
    int t  = threadIdx.x;
    int c  = t >> 4;
    int n  = t & 15;
    int gi = blockIdx.x * 16 + c;       // b*I + i
    int b  = gi / Ic;
    int i  = gi - b * Ic;
    float An = -expf(A_log[i * Nst + n]);
    float Dv = Dp[i];
    float h  = 0.f;
    for (int s = 0; s < Sc; s++) {
        int row = b * Sc + s;
        float dt = g_dt[(size_t)row * Ic + i];
        float xs = g_xs[(size_t)row * Ic + i];
        float Bn = g_proj[row * PROJW + Rc + n];
        float Cn = g_proj[row * PROJW + Rc + Nst + n];
        h = h * expf(dt * An) + dt * Bn * xs;
        float v = h * Cn;
        v += __shfl_xor_sync(0xffffffffu, v, 8);
        v += __shfl_xor_sync(0xffffffffu, v, 4);
        v += __shfl_xor_sync(0xffffffffu, v, 2);
        v += __shfl_xor_sync(0xffffffffu, v, 1);
        if (n == 0) {
            float z  = g_xz[(size_t)row * (2 * Ic) + Ic + i];
            float yv = (v + Dv * xs) * (z * sigmoidf_(z));
            g_y[(size_t)row * Ic + i] = yv;
        }
    }
}

// ---------------- rotary (in-place), HD=64 ----------------
__global__ void rotary_kernel(float* __restrict__ p, int nheads) {
    int idx = blockIdx.x * blockDim.x + threadIdx.x;
    int tot = Mrows * nheads * 32;
    if (idx >= tot) return;
    int r    = idx / (nheads * 32);
    int rem  = idx - r * (nheads * 32);
    int head = rem >> 5;
    int j    = rem & 31;
    int s    = r % Sc;
    float inv = expf(-((float)(2 * j) / (float)HDc) * logf(10000.0f));
    float f = (float)s * inv;
    float sn, cs;
    sincosf(f, &sn, &cs);
    float* base = p + (size_t)r * nheads * HDc + head * HDc;
    float x1 = base[j], x2 = base[j + 32];
    base[j]      = x1 * cs - x2 * sn;
    base[j + 32] = x2 * cs + x1 * sn;
}

// ---------------- dual-window attention, warp per query ----------------
__global__ void attn_kernel() {
    __shared__ float sc[8][WATT + WSSM];
    int t    = threadIdx.x;
    int warp = t >> 5;
    int lane = t & 31;
    int blk  = blockIdx.x;
    int qblk = blk % (Sc / 8);
    int bh   = blk / (Sc / 8);
    int h    = bh % NHc;
    int b    = bh / NHc;
    int qi   = qblk * 8 + warp;
    int row  = b * Sc + qi;
    int hk   = h / (NHc / NKVc);

    const float* qp = g_q + (size_t)row * NHc * HDc + h * HDc;
    float q0 = qp[lane], q1 = qp[lane + 32];

    int ka = max(0, qi - (WATT - 1));
    int na = qi - ka + 1;
    int ks = max(0, qi - (WSSM - 1));
    int ns = qi - ks + 1;

    for (int j = 0; j < na; j++) {
        const float* kp = g_katt + (size_t)(b * Sc + ka + j) * NKVc * HDc + hk * HDc;
        float d = q0 * kp[lane] + q1 * kp[lane + 32];
#pragma unroll
        for (int off = 16; off; off >>= 1) d += __shfl_xor_sync(0xffffffffu, d, off);
        if (lane == 0) sc[warp][j] = d * 0.125f;
    }
    for (int j = 0; j < ns; j++) {
        const float* kp = g_kssm + (size_t)(b * Sc + ks + j) * NKVc * HDc + hk * HDc;
        float d = q0 * kp[lane] + q1 * kp[lane + 32];
#pragma unroll
        for (int off = 16; off; off >>= 1) d += __shfl_xor_sync(0xffffffffu, d, off);
        if (lane == 0) sc[warp][WATT + j] = d * 0.125f;
    }
    __syncwarp();

    float mx = -1e30f;
    for (int j = lane; j < na; j += 32) mx = fmaxf(mx, sc[warp][j]);
    for (int j = lane; j < ns; j += 32) mx = fmaxf(mx, sc[warp][WATT + j]);
#pragma unroll
    for (int off = 16; off; off >>= 1) mx = fmaxf(mx, __shfl_xor_sync(0xffffffffu, mx, off));

    float sum = 0.f;
    for (int j = lane; j < na; j += 32) {
        float e = expf(sc[warp][j] - mx);
        sc[warp][j] = e; sum += e;
    }
    for (int j = lane; j < ns; j += 32) {
        float e = expf(sc[warp][WATT + j] - mx);
        sc[warp][WATT + j] = e; sum += e;
    }
#pragma unroll
    for (int off = 16; off; off >>= 1) sum += __shfl_xor_sync(0xffffffffu, sum, off);
    float invs = 1.f / sum;
    __syncwarp();

    float o0 = 0.f, o1 = 0.f;
    for (int j = 0; j < na; j++) {
        float p = sc[warp][j];
        const float* vp = g_vatt + (size_t)(b * Sc + ka + j) * NKVc * HDc + hk * HDc;
        o0 = fmaf(p, vp[lane], o0);
        o1 = fmaf(p, vp[lane + 32], o1);
    }
    for (int j = 0; j < ns; j++) {
        float p = sc[warp][WATT + j];
        const float* vp = g_vssm + (size_t)(b * Sc + ks + j) * NKVc * HDc + hk * HDc;
        o0 = fmaf(p, vp[lane], o0);
        o1 = fmaf(p, vp[lane + 32], o1);
    }
    float* op = g_o + (size_t)row * NHc * HDc + h * HDc;
    op[lane]      = o0 * invs;
    op[lane + 32] = o1 * invs;
}

// ---------------- SwiGLU ----------------
__global__ void swiglu_kernel() {
    int idx = blockIdx.x * blockDim.x + threadIdx.x;
    if (idx >= Mrows * IMc) return;
    int row = idx / IMc;
    int c   = idx - row * IMc;
    float g = g_gv[(size_t)row * (2 * IMc) + c];
    float v = g_gv[(size_t)row * (2 * IMc) + IMc + c];
    g_hm[idx] = g * sigmoidf_(g) * v;
}

// ---------------- final residual add (d_out += mlp_residual) ----------------
__global__ void final_add(float* __restrict__ out) {
    int idx = blockIdx.x * blockDim.x + threadIdx.x;
    if (idx >= Mrows * Hc) return;
    out[idx] += g_mlpres[idx];
}

// ---------------- host launcher ----------------
extern "C" void kernel_launch(void* const* d_in, const int* in_sizes, int n_in,
                              void* d_out, int out_size) {
    const float* hidden      = (const float*)d_in[0];
    const float* pre_norm_w  = (const float*)d_in[1];
    const float* in_proj_w   = (const float*)d_in[2];
    const float* conv_w      = (const float*)d_in[3];
    const float* conv_b      = (const float*)d_in[4];
    const float* x_proj_w    = (const float*)d_in[5];
    const float* dt_proj_w   = (const float*)d_in[6];
    const float* dt_proj_b   = (const float*)d_in[7];
    const float* A_log       = (const float*)d_in[8];
    const float* Dp          = (const float*)d_in[9];
    const float* out_proj_w  = (const float*)d_in[10];
    const float* ssm_norm_w  = (const float*)d_in[11];
    const float* q_w         = (const float*)d_in[12];
    const float* k_w         = (const float*)d_in[13];
    const float* v_w         = (const float*)d_in[14];
    const float* o_w         = (const float*)d_in[15];
    const float* mlp_norm_w  = (const float*)d_in[16];
    const float* gate_w      = (const float*)d_in[17];
    const float* down_w      = (const float*)d_in[18];
    float* out = (float*)d_out;

    float *hs, *xz, *xs, *proj, *dt, *y, *tmp, *ssmres, *ssmst;
    float *q, *katt, *vatt, *kssm, *vssm, *o, *mlpres, *x2, *gv, *hm;
    cudaGetSymbolAddress((void**)&hs, g_hs);
    cudaGetSymbolAddress((void**)&xz, g_xz);
    cudaGetSymbolAddress((void**)&xs, g_xs);
    cudaGetSymbolAddress((void**)&proj, g_proj);
    cudaGetSymbolAddress((void**)&dt, g_dt);
    cudaGetSymbolAddress((void**)&y, g_y);
    cudaGetSymbolAddress((void**)&tmp, g_tmp);
    cudaGetSymbolAddress((void**)&ssmres, g_ssmres);
    cudaGetSymbolAddress((void**)&ssmst, g_ssmst);
    cudaGetSymbolAddress((void**)&q, g_q);
    cudaGetSymbolAddress((void**)&katt, g_katt);
    cudaGetSymbolAddress((void**)&vatt, g_vatt);
    cudaGetSymbolAddress((void**)&kssm, g_kssm);
    cudaGetSymbolAddress((void**)&vssm, g_vssm);
    cudaGetSymbolAddress((void**)&o, g_o);
    cudaGetSymbolAddress((void**)&mlpres, g_mlpres);
    cudaGetSymbolAddress((void**)&x2, g_x2);
    cudaGetSymbolAddress((void**)&gv, g_gv);
    cudaGetSymbolAddress((void**)&hm, g_hm);

    // 1. pre-norm
    resid_rms<<<Mrows, 256>>>(hidden, nullptr, pre_norm_w, nullptr, hs);
    // 2. in_proj: xz = hs @ in_proj_w^T    (2048 x 4096, K=1024)
    gemm_nt<<<dim3(4096 / BN, Mrows / BM), 256>>>(hs, in_proj_w, xz, Mrows, 4096, Hc, Hc, Hc);
    // 3. conv + silu
    conv_silu<<<(Mrows * Ic) / 256, 256>>>(conv_w, conv_b);
    // 4. x_proj: proj = xs @ x_proj_w^T    (2048 x 96, K=2048)
    gemm_nt<<<dim3(2, Mrows / BM), 256>>>(xs, x_proj_w, proj, Mrows, PROJW, Ic, Ic, Ic);
    // 5. dt raw = proj[:, :64] @ dt_proj_w^T  (2048 x 2048, K=64, lda=96)
    gemm_nt<<<dim3(Ic / BN, Mrows / BM), 256>>>(proj, dt_proj_w, dt, Mrows, Ic, Rc, PROJW, Rc);
    bias_softplus<<<(Mrows * Ic) / 256, 256>>>(dt_proj_b);
    // 6. selective scan -> g_y (includes D*xs and silu(z) gate)
    scan_kernel<<<(Bc * Ic) / 16, 256>>>(A_log, Dp);
    // 7. ssm_out = y @ out_proj_w^T (2048 x 1024, K=2048); residual + norm
    gemm_nt<<<dim3(Hc / BN, Mrows / BM), 256>>>(y, out_proj_w, tmp, Mrows, Hc, Ic, Ic, Ic);
    resid_rms<<<Mrows, 256>>>(tmp, hidden, ssm_norm_w, ssmres, ssmst);
    // 8. q/k/v projections
    gemm_nt<<<dim3((NHc * HDc) / BN, Mrows / BM), 256>>>(hs, q_w, q, Mrows, NHc * HDc, Hc, Hc, Hc);
    gemm_nt<<<dim3((NKVc * HDc) / BN, Mrows / BM), 256>>>(hs, k_w, katt, Mrows, NKVc * HDc, Hc, Hc, Hc);
    gemm_nt<<<dim3((NKVc * HDc) / BN, Mrows / BM), 256>>>(hs, v_w, vatt, Mrows, NKVc * HDc, Hc, Hc, Hc);
    gemm_nt<<<dim3((NKVc * HDc) / BN, Mrows / BM), 256>>>(ssmst, k_w, kssm, Mrows, NKVc * HDc, Hc, Hc, Hc);
    gemm_nt<<<dim3((NKVc * HDc) / BN, Mrows / BM), 256>>>(ssmst, v_w, vssm, Mrows, NKVc * HDc, Hc, Hc, Hc);
    // 9. rotary
    rotary_kernel<<<(Mrows * NHc * 32) / 256, 256>>>(q, NHc);
    rotary_kernel<<<(Mrows * NKVc * 32) / 256, 256>>>(katt, NKVc);
    rotary_kernel<<<(Mrows * NKVc * 32) / 256, 256>>>(kssm, NKVc);
    // 10. attention
    attn_kernel<<<Bc * NHc * (Sc / 8), 256>>>();
    // 11. o proj; residual + norm
    gemm_nt<<<dim3(Hc / BN, Mrows / BM), 256>>>(o, o_w, tmp, Mrows, Hc, NHc * HDc, NHc * HDc, NHc * HDc);
    resid_rms<<<Mrows, 256>>>(tmp, ssmres, mlp_norm_w, mlpres, x2);
    // 12. MLP
    gemm_nt<<<dim3((2 * IMc) / BN, Mrows / BM), 256>>>(x2, gate_w, gv, Mrows, 2 * IMc, Hc, Hc, Hc);
    swiglu_kernel<<<(Mrows * IMc) / 256, 256>>>();
    gemm_nt<<<dim3(Hc / BN, Mrows / BM), 256>>>(hm, down_w, out, Mrows, Hc, IMc, IMc, IMc);
    final_add<<<(Mrows * Hc) / 256, 256>>>(out);
}

// round 3
// speedup vs baseline: 1.4340x; 1.4340x over previous
#include <cuda_runtime.h>
#include <math.h>
#include <stdint.h>

// ---------------- problem constants ----------------
#define Bc   2
#define Sc   1024
#define Hc   1024
#define Ic   2048
#define Nst  16
#define Rc   64
#define Kcv  4
#define NHc  16
#define NKVc 4
#define HDc  64
#define WATT 512
#define WSSM 128
#define IMc  2816
#define Mrows (Bc*Sc)        // 2048
#define EPSc  1e-6f
#define PROJW (Rc + 2*Nst)   // 96
#define QKVLD 1536           // q(1024)|katt(256)|vatt(256)
#define KVSLD 512            // kssm(256)|vssm(256)

// ---------------- scratch (static device globals; no allocation) ----------------
__device__ float g_hs[Mrows*Hc];
__device__ float g_xz[Mrows*2*Ic];
__device__ float g_xs[Mrows*Ic];
__device__ float g_proj[Mrows*PROJW];
__device__ float g_dt[Mrows*Ic];
__device__ float g_y[Mrows*Ic];
__device__ float g_tmp[Mrows*Hc];
__device__ float g_ssmres[Mrows*Hc];
__device__ float g_ssmst[Mrows*Hc];
__device__ float g_qkv[Mrows*QKVLD];
__device__ float g_kvssm[Mrows*KVSLD];
__device__ float g_o[Mrows*NHc*HDc];
__device__ float g_mlpres[Mrows*Hc];
__device__ float g_x2[Mrows*Hc];
__device__ float g_gv[Mrows*2*IMc];
__device__ float g_hm[Mrows*IMc];
__device__ float g_wqkv[QKVLD*Hc];
__device__ float g_wkv[KVSLD*Hc];

__device__ __forceinline__ float sigmoidf_(float x) { return 1.f / (1.f + expf(-x)); }

// ---------------- tf32 tensor-core GEMM: C[m,n] = sum_k A[m,k]*B[n,k] ----------------
// BM=128, BN=128, BK=32, 256 threads, warp grid 4(M) x 2(N), warp tile 32x64.
#define BM 128
#define BN 128
#define BK 32
#define PADS 36   // BK + 4 pad -> conflict-free fragment LDS
#define SM_FLOATS (4*4608)   // 2 bufs x (A 128*36 + B 128*36)

__device__ __forceinline__ void cp16(uint32_t dst, const float* src, int ssize) {
    asm volatile("cp.async.cg.shared.global [%0], [%1], 16, %2;\n"
                 :: "r"(dst), "l"(src), "r"(ssize));
}
__device__ __forceinline__ uint32_t f2tf32(float x) {
    uint32_t u; asm("cvt.rna.tf32.f32 %0, %1;" : "=r"(u) : "f"(x)); return u;
}
__device__ __forceinline__ void mma_tf32(float* c, const uint32_t* a, uint32_t b0, uint32_t b1) {
    asm volatile("mma.sync.aligned.m16n8k8.row.col.f32.tf32.tf32.f32 "
                 "{%0,%1,%2,%3}, {%4,%5,%6,%7}, {%8,%9}, {%0,%1,%2,%3};\n"
                 : "+f"(c[0]), "+f"(c[1]), "+f"(c[2]), "+f"(c[3])
                 : "r"(a[0]), "r"(a[1]), "r"(a[2]), "r"(a[3]), "r"(b0), "r"(b1));
}

__global__ __launch_bounds__(256, 2)
void gemm_tf32(const float* __restrict__ A, const float* __restrict__ Bw,
               float* __restrict__ C, int Mdim, int Ndim, int Kdim, int lda, int ldb) {
    extern __shared__ float sm[];
    const int t    = threadIdx.x;
    const int bm   = blockIdx.y * BM;
    const int bn   = blockIdx.x * BN;
    const int warp = t >> 5, lane = t & 31;
    const int wm   = (warp & 3) * 32;
    const int wn   = (warp >> 2) * 64;
    const int gid  = lane >> 2;
    const int tig  = lane & 3;
    const uint32_t smem_base = (uint32_t)__cvta_generic_to_shared(sm);

    float acc[2][8][4];
#pragma unroll
    for (int mi = 0; mi < 2; mi++)
#pragma unroll
        for (int ni = 0; ni < 8; ni++)
#pragma unroll
            for (int j = 0; j < 4; j++) acc[mi][ni][j] = 0.f;

    const int niters = Kdim / BK;

    // tile loader: 1024 float4 per (A,B) pair, 4 each per thread
    auto load_tile = [&](int buf, int k0) {
        uint32_t aOff = smem_base + buf * 9216 * 4;
        uint32_t bOff = aOff + 4608 * 4;
#pragma unroll
        for (int i = 0; i < 4; i++) {
            int id = t + i * 256;
            int r  = id >> 3;
            int kq = (id & 7) * 4;
            cp16(aOff + (r * PADS + kq) * 4,
                 A + (size_t)(bm + r) * lda + k0 + kq, 16);
            int br = bn + r;
            int ok = (br < Ndim);
            cp16(bOff + (r * PADS + kq) * 4,
                 Bw + (size_t)(ok ? br : 0) * ldb + k0 + kq, ok ? 16 : 0);
        }
    };

    load_tile(0, 0);
    asm volatile("cp.async.commit_group;\n");

    for (int it = 0; it < niters; it++) {
        if (it + 1 < niters) {
            load_tile((it + 1) & 1, (it + 1) * BK);
            asm volatile("cp.async.commit_group;\n");
            asm volatile("cp.async.wait_group 1;\n");
        } else {
            asm volatile("cp.async.wait_group 0;\n");
        }
        __syncthreads();

        const float* Ab = sm + (it & 1) * 9216;
        const float* Bb = Ab + 4608;
#pragma unroll
        for (int kk = 0; kk < 4; kk++) {
            int kb = kk * 8;
            uint32_t afr[2][4];
#pragma unroll
            for (int mi = 0; mi < 2; mi++) {
                const float* ab = Ab + (wm + mi * 16 + gid) * PADS + kb + tig;
                afr[mi][0] = f2tf32(ab[0]);
                afr[mi][1] = f2tf32(ab[8 * PADS]);
                afr[mi][2] = f2tf32(ab[4]);
                afr[mi][3] = f2tf32(ab[8 * PADS + 4]);
            }
#pragma unroll
            for (int ni = 0; ni < 8; ni++) {
                const float* bb = Bb + (wn + ni * 8 + gid) * PADS + kb + tig;
                uint32_t b0 = f2tf32(bb[0]);
                uint32_t b1 = f2tf32(bb[4]);
#pragma unroll
                for (int mi = 0; mi < 2; mi++)
                    mma_tf32(acc[mi][ni], afr[mi], b0, b1);
            }
        }
        __syncthreads();
    }

    // epilogue
#pragma unroll
    for (int mi = 0; mi < 2; mi++) {
        int r0 = bm + wm + mi * 16 + gid;
#pragma unroll
        for (int ni = 0; ni < 8; ni++) {
            int c0 = bn + wn + ni * 8 + tig * 2;
            if (c0 < Ndim) {
                *(float2*)(C + (size_t)r0 * Ndim + c0) =
                    make_float2(acc[mi][ni][0], acc[mi][ni][1]);
                *(float2*)(C + (size_t)(r0 + 8) * Ndim + c0) =
                    make_float2(acc[mi][ni][2], acc[mi][ni][3]);
            }
        }
    }
}

// ---------------- weight concat (per-call, cheap) ----------------
__global__ void concat_qkv_w(const float* __restrict__ qw, const float* __restrict__ kw,
                             const float* __restrict__ vw) {
    int idx = blockIdx.x * 256 + threadIdx.x;
    if (idx >= QKVLD * Hc) return;
    int row = idx >> 10, col = idx & 1023;
    float v;
    if (row < 1024)      v = qw[idx];
    else if (row < 1280) v = kw[(row - 1024) * Hc + col];
    else                 v = vw[(row - 1280) * Hc + col];
    g_wqkv[idx] = v;
}
__global__ void concat_kv_w(const float* __restrict__ kw, const float* __restrict__ vw) {
    int idx = blockIdx.x * 256 + threadIdx.x;
    if (idx >= KVSLD * Hc) return;
    int row = idx >> 10, col = idx & 1023;
    g_wkv[idx] = (row < 256) ? kw[row * Hc + col] : vw[(row - 256) * Hc + col];
}

// ---------------- RMSNorm (optional residual add) over 1024 cols ----------------
__global__ void resid_rms(const float* __restrict__ a, const float* __restrict__ r,
                          const float* __restrict__ w, float* __restrict__ res_out,
                          float* __restrict__ nrm_out) {
    int row = blockIdx.x;
    int t   = threadIdx.x;
    const float* ap = a + (size_t)row * Hc;
    const float* rp = r ? r + (size_t)row * Hc : nullptr;
    float v[4];
    float ss = 0.f;
#pragma unroll
    for (int i = 0; i < 4; i++) {
        int c = t + i * 256;
        float x = ap[c] + (rp ? rp[c] : 0.f);
        v[i] = x;
        ss += x * x;
    }
#pragma unroll
    for (int off = 16; off; off >>= 1) ss += __shfl_xor_sync(0xffffffffu, ss, off);
    __shared__ float sred[8];
    __shared__ float sscale;
    if ((t & 31) == 0) sred[t >> 5] = ss;
    __syncthreads();
    if (t == 0) {
        float tot = 0.f;
        for (int i = 0; i < 8; i++) tot += sred[i];
        sscale = rsqrtf(tot * (1.f / Hc) + EPSc);
    }
    __syncthreads();
    float scale = sscale;
    float* ro = res_out ? res_out + (size_t)row * Hc : nullptr;
    float* no = nrm_out + (size_t)row * Hc;
#pragma unroll
    for (int i = 0; i < 4; i++) {
        int c = t + i * 256;
        if (ro) ro[c] = v[i];
        no[c] = v[i] * scale * w[c];
    }
}

// ---------------- causal depthwise conv (K=4) + SiLU ----------------
__global__ void conv_silu(const float* __restrict__ cw, const float* __restrict__ cb) {
    int idx = blockIdx.x * blockDim.x + threadIdx.x;
    if (idx >= Mrows * Ic) return;
    int row = idx / Ic;
    int i   = idx - row * Ic;
    int b   = row / Sc;
    int s   = row - b * Sc;
    float acc = cb[i];
#pragma unroll
    for (int k = 0; k < Kcv; k++) {
        int sp = s + k - (Kcv - 1);
        if (sp >= 0)
            acc += cw[i * Kcv + k] * g_xz[(size_t)(b * Sc + sp) * (2 * Ic) + i];
    }
    g_xs[idx] = acc * sigmoidf_(acc);
}

// ---------------- dt bias + softplus (in place on g_dt) ----------------
__global__ void bias_softplus(const float* __restrict__ dtb) {
    int idx = blockIdx.x * blockDim.x + threadIdx.x;
    if (idx >= Mrows * Ic) return;
    int i = idx % Ic;
    float x = g_dt[idx] + dtb[i];
    g_dt[idx] = (x > 20.f) ? x : log1pf(expf(x));
}

// ---------------- selective scan ----------------
__global__ void scan_kernel(const float* __restrict__ A_log, const float* __restrict__ Dp) {
    int t  = threadIdx.x;
    int c  = t >> 4;
    int n  = t & 15;
    int gi = blockIdx.x * 16 + c;       // b*I + i
    int b  = gi / Ic;
    int i  = gi - b * Ic;
    float An = -expf(A_log[i * Nst + n]);
    float Dv = Dp[i];
    float h  = 0.f;
    for (int s = 0; s < Sc; s++) {
        int row = b * Sc + s;
        float dt = g_dt[(size_t)row * Ic + i];
        float xs = g_xs[(size_t)row * Ic + i];
        float Bn = g_proj[row * PROJW + Rc + n];
        float Cn = g_proj[row * PROJW + Rc + Nst + n];
        h = h * expf(dt * An) + dt * Bn * xs;
        float v = h * Cn;
        v += __shfl_xor_sync(0xffffffffu, v, 8);
        v += __shfl_xor_sync(0xffffffffu, v, 4);
        v += __shfl_xor_sync(0xffffffffu, v, 2);
        v += __shfl_xor_sync(0xffffffffu, v, 1);
        if (n == 0) {
            float z  = g_xz[(size_t)row * (2 * Ic) + Ic + i];
            float yv = (v + Dv * xs) * (z * sigmoidf_(z));
            g_y[(size_t)row * Ic + i] = yv;
        }
    }
}

// ---------------- rotary (in-place, strided view), HD=64 ----------------
__global__ void rotary_kernel(float* __restrict__ p, int ld, int coloff, int nheads) {
    int idx = blockIdx.x * blockDim.x + threadIdx.x;
    int tot = Mrows * nheads * 32;
    if (idx >= tot) return;
    int r    = idx / (nheads * 32);
    int rem  = idx - r * (nheads * 32);
    int head = rem >> 5;
    int j    = rem & 31;
    int s    = r % Sc;
    float inv = expf(-((float)(2 * j) / (float)HDc) * logf(10000.0f));
    float f = (float)s * inv;
    float sn, cs;
    sincosf(f, &sn, &cs);
    float* base = p + (size_t)r * ld + coloff + head * HDc;
    float x1 = base[j], x2 = base[j + 32];
    base[j]      = x1 * cs - x2 * sn;
    base[j + 32] = x2 * cs + x1 * sn;
}

// ---------------- dual-window attention, warp per query ----------------
__global__ void attn_kernel() {
    __shared__ float sc[8][WATT + WSSM];
    int t    = threadIdx.x;
    int warp = t >> 5;
    int lane = t & 31;
    int blk  = blockIdx.x;
    int qblk = blk % (Sc / 8);
    int bh   = blk / (Sc / 8);
    int h    = bh % NHc;
    int b    = bh / NHc;
    int qi   = qblk * 8 + warp;
    int row  = b * Sc + qi;
    int hk   = h / (NHc / NKVc);

    const float* qp = g_qkv + (size_t)row * QKVLD + h * HDc;
    float q0 = qp[lane], q1 = qp[lane + 32];

    int ka = max(0, qi - (WATT - 1));
    int na = qi - ka + 1;
    int ks = max(0, qi - (WSSM - 1));
    int ns = qi - ks + 1;

    for (int j = 0; j < na; j++) {
        const float* kp = g_qkv + (size_t)(b * Sc + ka + j) * QKVLD + 1024 + hk * HDc;
        float d = q0 * kp[lane] + q1 * kp[lane + 32];
#pragma unroll
        for (int off = 16; off; off >>= 1) d += __shfl_xor_sync(0xffffffffu, d, off);
        if (lane == 0) sc[warp][j] = d * 0.125f;
    }
    for (int j = 0; j < ns; j++) {
        const float* kp = g_kvssm + (size_t)(b * Sc + ks + j) * KVSLD + hk * HDc;
        float d = q0 * kp[lane] + q1 * kp[lane + 32];
#pragma unroll
        for (int off = 16; off; off >>= 1) d += __shfl_xor_sync(0xffffffffu, d, off);
        if (lane == 0) sc[warp][WATT + j] = d * 0.125f;
    }
    __syncwarp();

    float mx = -1e30f;
    for (int j = lane; j < na; j += 32) mx = fmaxf(mx, sc[warp][j]);
    for (int j = lane; j < ns; j += 32) mx = fmaxf(mx, sc[warp][WATT + j]);
#pragma unroll
    for (int off = 16; off; off >>= 1) mx = fmaxf(mx, __shfl_xor_sync(0xffffffffu, mx, off));

    float sum = 0.f;
    for (int j = lane; j < na; j += 32) {
        float e = expf(sc[warp][j] - mx);
        sc[warp][j] = e; sum += e;
    }
    for (int j = lane; j < ns; j += 32) {
        float e = expf(sc[warp][WATT + j] - mx);
        sc[warp][WATT + j] = e; sum += e;
    }
#pragma unroll
    for (int off = 16; off; off >>= 1) sum += __shfl_xor_sync(0xffffffffu, sum, off);
    float invs = 1.f / sum;
    __syncwarp();

    float o0 = 0.f, o1 = 0.f;
    for (int j = 0; j < na; j++) {
        float p = sc[warp][j];
        const float* vp = g_qkv + (size_t)(b * Sc + ka + j) * QKVLD + 1280 + hk * HDc;
        o0 = fmaf(p, vp[lane], o0);
        o1 = fmaf(p, vp[lane + 32], o1);
    }
    for (int j = 0; j < ns; j++) {
        float p = sc[warp][WATT + j];
        const float* vp = g_kvssm + (size_t)(b * Sc + ks + j) * KVSLD + 256 + hk * HDc;
        o0 = fmaf(p, vp[lane], o0);
        o1 = fmaf(p, vp[lane + 32], o1);
    }
    float* op = g_o + (size_t)row * NHc * HDc + h * HDc;
    op[lane]      = o0 * invs;
    op[lane + 32] = o1 * invs;
}

// ---------------- SwiGLU ----------------
__global__ void swiglu_kernel() {
    int idx = blockIdx.x * blockDim.x + threadIdx.x;
    if (idx >= Mrows * IMc) return;
    int row = idx / IMc;
    int c   = idx - row * IMc;
    float g = g_gv[(size_t)row * (2 * IMc) + c];
    float v = g_gv[(size_t)row * (2 * IMc) + IMc + c];
    g_hm[idx] = g * sigmoidf_(g) * v;
}

// ---------------- final residual add (d_out += mlp_residual) ----------------
__global__ void final_add(float* __restrict__ out) {
    int idx = blockIdx.x * blockDim.x + threadIdx.x;
    if (idx >= Mrows * Hc) return;
    out[idx] += g_mlpres[idx];
}

// ---------------- host launcher ----------------
extern "C" void kernel_launch(void* const* d_in, const int* in_sizes, int n_in,
                              void* d_out, int out_size) {
    const float* hidden      = (const float*)d_in[0];
    const float* pre_norm_w  = (const float*)d_in[1];
    const float* in_proj_w   = (const float*)d_in[2];
    const float* conv_w      = (const float*)d_in[3];
    const float* conv_b      = (const float*)d_in[4];
    const float* x_proj_w    = (const float*)d_in[5];
    const float* dt_proj_w   = (const float*)d_in[6];
    const float* dt_proj_b   = (const float*)d_in[7];
    const float* A_log       = (const float*)d_in[8];
    const float* Dp          = (const float*)d_in[9];
    const float* out_proj_w  = (const float*)d_in[10];
    const float* ssm_norm_w  = (const float*)d_in[11];
    const float* q_w         = (const float*)d_in[12];
    const float* k_w         = (const float*)d_in[13];
    const float* v_w         = (const float*)d_in[14];
    const float* o_w         = (const float*)d_in[15];
    const float* mlp_norm_w  = (const float*)d_in[16];
    const float* gate_w      = (const float*)d_in[17];
    const float* down_w      = (const float*)d_in[18];
    float* out = (float*)d_out;

    const int smem_bytes = SM_FLOATS * 4;   // 73728
    cudaFuncSetAttribute(gemm_tf32, cudaFuncAttributeMaxDynamicSharedMemorySize, smem_bytes);

    float *hs, *xz, *xs, *proj, *dt, *y, *tmp, *ssmres, *ssmst;
    float *qkv, *kvssm, *o, *mlpres, *x2, *gv, *hm, *wqkv, *wkv;
    cudaGetSymbolAddress((void**)&hs, g_hs);
    cudaGetSymbolAddress((void**)&xz, g_xz);
    cudaGetSymbolAddress((void**)&xs, g_xs);
    cudaGetSymbolAddress((void**)&proj, g_proj);
    cudaGetSymbolAddress((void**)&dt, g_dt);
    cudaGetSymbolAddress((void**)&y, g_y);
    cudaGetSymbolAddress((void**)&tmp, g_tmp);
    cudaGetSymbolAddress((void**)&ssmres, g_ssmres);
    cudaGetSymbolAddress((void**)&ssmst, g_ssmst);
    cudaGetSymbolAddress((void**)&qkv, g_qkv);
    cudaGetSymbolAddress((void**)&kvssm, g_kvssm);
    cudaGetSymbolAddress((void**)&o, g_o);
    cudaGetSymbolAddress((void**)&mlpres, g_mlpres);
    cudaGetSymbolAddress((void**)&x2, g_x2);
    cudaGetSymbolAddress((void**)&gv, g_gv);
    cudaGetSymbolAddress((void**)&hm, g_hm);
    cudaGetSymbolAddress((void**)&wqkv, g_wqkv);
    cudaGetSymbolAddress((void**)&wkv, g_wkv);

    // 0. weight concats (q|k|v and k|v)
    concat_qkv_w<<<(QKVLD * Hc + 255) / 256, 256>>>(q_w, k_w, v_w);
    concat_kv_w<<<(KVSLD * Hc + 255) / 256, 256>>>(k_w, v_w);

    // 1. pre-norm
    resid_rms<<<Mrows, 256>>>(hidden, nullptr, pre_norm_w, nullptr, hs);
    // 2. in_proj: xz = hs @ in_proj_w^T  (2048 x 4096, K=1024)
    gemm_tf32<<<dim3(4096 / BN, Mrows / BM), 256, smem_bytes>>>(hs, in_proj_w, xz, Mrows, 4096, Hc, Hc, Hc);
    // 3. conv + silu
    conv_silu<<<(Mrows * Ic) / 256, 256>>>(conv_w, conv_b);
    // 4. x_proj: proj = xs @ x_proj_w^T  (2048 x 96, K=2048)
    gemm_tf32<<<dim3(1, Mrows / BM), 256, smem_bytes>>>(xs, x_proj_w, proj, Mrows, PROJW, Ic, Ic, Ic);
    // 5. dt = proj[:, :64] @ dt_proj_w^T (2048 x 2048, K=64, lda=96)
    gemm_tf32<<<dim3(Ic / BN, Mrows / BM), 256, smem_bytes>>>(proj, dt_proj_w, dt, Mrows, Ic, Rc, PROJW, Rc);
    bias_softplus<<<(Mrows * Ic) / 256, 256>>>(dt_proj_b);
    // 6. selective scan -> g_y (includes D*xs and silu(z) gate)
    scan_kernel<<<(Bc * Ic) / 16, 256>>>(A_log, Dp);
    // 7. ssm_out = y @ out_proj_w^T (2048 x 1024, K=2048); residual + norm
    gemm_tf32<<<dim3(Hc / BN, Mrows / BM), 256, smem_bytes>>>(y, out_proj_w, tmp, Mrows, Hc, Ic, Ic, Ic);
    resid_rms<<<Mrows, 256>>>(tmp, hidden, ssm_norm_w, ssmres, ssmst);
    // 8. fused qkv projections
    gemm_tf32<<<dim3(QKVLD / BN, Mrows / BM), 256, smem_bytes>>>(hs, wqkv, qkv, Mrows, QKVLD, Hc, Hc, Hc);
    gemm_tf32<<<dim3(KVSLD / BN, Mrows / BM), 256, smem_bytes>>>(ssmst, wkv, kvssm, Mrows, KVSLD, Hc, Hc, Hc);
    // 9. rotary on q, k_att, k_ssm
    rotary_kernel<<<(Mrows * NHc * 32) / 256, 256>>>(qkv, QKVLD, 0, NHc);
    rotary_kernel<<<(Mrows * NKVc * 32) / 256, 256>>>(qkv, QKVLD, 1024, NKVc);
    rotary_kernel<<<(Mrows * NKVc * 32) / 256, 256>>>(kvssm, KVSLD, 0, NKVc);
    // 10. attention
    attn_kernel<<<Bc * NHc * (Sc / 8), 256>>>();
    // 11. o proj; residual + norm
    gemm_tf32<<<dim3(Hc / BN, Mrows / BM), 256, smem_bytes>>>(o, o_w, tmp, Mrows, Hc, NHc * HDc, NHc * HDc, NHc * HDc);
    resid_rms<<<Mrows, 256>>>(tmp, ssmres, mlp_norm_w, mlpres, x2);
    // 12. MLP
    gemm_tf32<<<dim3((2 * IMc) / BN, Mrows / BM), 256, smem_bytes>>>(x2, gate_w, gv, Mrows, 2 * IMc, Hc, Hc, Hc);
    swiglu_kernel<<<(Mrows * IMc) / 256, 256>>>();
    gemm_tf32<<<dim3(Hc / BN, Mrows / BM), 256, smem_bytes>>>(hm, down_w, out, Mrows, Hc, IMc, IMc, IMc);
    final_add<<<(Mrows * Hc) / 256, 256>>>(out);
}

// round 4
// speedup vs baseline: 2.3119x; 1.6122x over previous
#include <cuda_runtime.h>
#include <math.h>
#include <stdint.h>

// ---------------- problem constants ----------------
#define Bc   2
#define Sc   1024
#define Hc   1024
#define Ic   2048
#define Nst  16
#define Rc   64
#define Kcv  4
#define NHc  16
#define NKVc 4
#define HDc  64
#define WATT 512
#define WSSM 128
#define IMc  2816
#define Mrows (Bc*Sc)        // 2048
#define EPSc  1e-6f
#define PROJW (Rc + 2*Nst)   // 96
#define FUSN  5632           // xz(4096)|q(1024)|katt(256)|vatt(256)
#define KVSLD 512            // kssm(256)|vssm(256)

// ---------------- scratch (static device globals; no allocation) ----------------
__device__ float g_hs[Mrows*Hc];
__device__ float g_xzq[Mrows*FUSN];
__device__ float g_xs[Mrows*Ic];      // full precision (scan)
__device__ float g_xst[Mrows*Ic];     // tf32-rounded (x_proj GEMM)
__device__ float g_proj[Mrows*PROJW];
__device__ float g_dt[Mrows*Ic];
__device__ float g_y[Mrows*Ic];
__device__ float g_tmp[Mrows*Hc];
__device__ float g_ssmres[Mrows*Hc];
__device__ float g_ssmst[Mrows*Hc];
__device__ float g_kvssm[Mrows*KVSLD];
__device__ float g_o[Mrows*NHc*HDc];
__device__ float g_mlpres[Mrows*Hc];
__device__ float g_x2[Mrows*Hc];
__device__ float g_gv[Mrows*2*IMc];
__device__ float g_hm[Mrows*IMc];
// tf32-rounded weights
__device__ float g_wbig[FUSN*Hc];
__device__ float g_wxp[PROJW*Ic];
__device__ float g_wdt[Ic*Rc];
__device__ float g_wop[Hc*Ic];
__device__ float g_wkv[KVSLD*Hc];
__device__ float g_wo[Hc*NHc*HDc];
__device__ float g_wg[2*IMc*Hc];
__device__ float g_wd[Hc*IMc];

__device__ __forceinline__ float sigmoidf_(float x) { return 1.f / (1.f + expf(-x)); }
__device__ __forceinline__ uint32_t f2tf32(float x) {
    uint32_t u; asm("cvt.rna.tf32.f32 %0, %1;" : "=r"(u) : "f"(x)); return u;
}
__device__ __forceinline__ float roundtf(float x) { return __uint_as_float(f2tf32(x)); }

// ---------------- tf32 tensor-core GEMM: C[m,n] = sum_k A[m,k]*B[n,k] ----------------
// BM=128, BNT in {128,64}, BK=32, 256 threads, warp grid 4(M) x 2(N).
#define BM 128
#define BK 32
#define PADS 36

__device__ __forceinline__ void cp16(uint32_t dst, const float* src, int ssize) {
    asm volatile("cp.async.cg.shared.global [%0], [%1], 16, %2;\n"
                 :: "r"(dst), "l"(src), "r"(ssize));
}
__device__ __forceinline__ void mma_tf32(float* c, const uint32_t* a, uint32_t b0, uint32_t b1) {
    asm volatile("mma.sync.aligned.m16n8k8.row.col.f32.tf32.tf32.f32 "
                 "{%0,%1,%2,%3}, {%4,%5,%6,%7}, {%8,%9}, {%0,%1,%2,%3};\n"
                 : "+f"(c[0]), "+f"(c[1]), "+f"(c[2]), "+f"(c[3])
                 : "r"(a[0]), "r"(a[1]), "r"(a[2]), "r"(a[3]), "r"(b0), "r"(b1));
}

// CVTA: convert A fragments to tf32 in-loop (for raw A operands). B is always pre-rounded.
template<int BNT, bool CVTA>
__global__ __launch_bounds__(256, 2)
void gemm_t(const float* __restrict__ A, const float* __restrict__ Bw,
            float* __restrict__ C, int Ndim, int Kdim, int lda, int ldb) {
    constexpr int NI  = BNT / 16;               // ni tiles per warp
    constexpr int ASZ = BM * PADS;
    constexpr int BSZ = BNT * PADS;
    extern __shared__ float sm[];
    const int t    = threadIdx.x;
    const int bm   = blockIdx.y * BM;
    const int bn   = blockIdx.x * BNT;
    const int warp = t >> 5, lane = t & 31;
    const int wm   = (warp & 3) * 32;
    const int wn   = (warp >> 2) * (BNT / 2);
    const int gid  = lane >> 2;
    const int tig  = lane & 3;
    const uint32_t smem_base = (uint32_t)__cvta_generic_to_shared(sm);

    float acc[2][NI][4];
#pragma unroll
    for (int mi = 0; mi < 2; mi++)
#pragma unroll
        for (int ni = 0; ni < NI; ni++)
#pragma unroll
            for (int j = 0; j < 4; j++) acc[mi][ni][j] = 0.f;

    const int niters = Kdim / BK;

    auto load_tile = [&](int buf, int k0) {
        uint32_t aOff = smem_base + buf * (ASZ + BSZ) * 4;
        uint32_t bOff = aOff + ASZ * 4;
#pragma unroll
        for (int i = 0; i < 4; i++) {               // A: 1024 float4
            int id = t + i * 256;
            int r  = id >> 3;
            int kq = (id & 7) * 4;
            cp16(aOff + (r * PADS + kq) * 4, A + (size_t)(bm + r) * lda + k0 + kq, 16);
        }
#pragma unroll
        for (int i = 0; i < BNT / 32; i++) {        // B: BNT*8 float4
            int id = t + i * 256;
            int r  = id >> 3;
            int kq = (id & 7) * 4;
            int br = bn + r;
            int ok = (br < Ndim);
            cp16(bOff + (r * PADS + kq) * 4, Bw + (size_t)(ok ? br : 0) * ldb + k0 + kq, ok ? 16 : 0);
        }
    };

    load_tile(0, 0);
    asm volatile("cp.async.commit_group;\n");

    for (int it = 0; it < niters; it++) {
        if (it + 1 < niters) {
            load_tile((it + 1) & 1, (it + 1) * BK);
            asm volatile("cp.async.commit_group;\n");
            asm volatile("cp.async.wait_group 1;\n");
        } else {
            asm volatile("cp.async.wait_group 0;\n");
        }
        __syncthreads();

        const float* Ab = sm + (it & 1) * (ASZ + BSZ);
        const float* Bb = Ab + ASZ;
#pragma unroll
        for (int kk = 0; kk < 4; kk++) {
            int kb = kk * 8;
            uint32_t afr[2][4];
#pragma unroll
            for (int mi = 0; mi < 2; mi++) {
                const float* ab = Ab + (wm + mi * 16 + gid) * PADS + kb + tig;
                if (CVTA) {
                    afr[mi][0] = f2tf32(ab[0]);
                    afr[mi][1] = f2tf32(ab[8 * PADS]);
                    afr[mi][2] = f2tf32(ab[4]);
                    afr[mi][3] = f2tf32(ab[8 * PADS + 4]);
                } else {
                    afr[mi][0] = __float_as_uint(ab[0]);
                    afr[mi][1] = __float_as_uint(ab[8 * PADS]);
                    afr[mi][2] = __float_as_uint(ab[4]);
                    afr[mi][3] = __float_as_uint(ab[8 * PADS + 4]);
                }
            }
#pragma unroll
            for (int ni = 0; ni < NI; ni++) {
                const float* bb = Bb + (wn + ni * 8 + gid) * PADS + kb + tig;
                uint32_t b0 = __float_as_uint(bb[0]);
                uint32_t b1 = __float_as_uint(bb[4]);
#pragma unroll
                for (int mi = 0; mi < 2; mi++)
                    mma_tf32(acc[mi][ni], afr[mi], b0, b1);
            }
        }
        __syncthreads();
    }

#pragma unroll
    for (int mi = 0; mi < 2; mi++) {
        int r0 = bm + wm + mi * 16 + gid;
#pragma unroll
        for (int ni = 0; ni < NI; ni++) {
            int c0 = bn + wn + ni * 8 + tig * 2;
            if (c0 < Ndim) {
                *(float2*)(C + (size_t)r0 * Ndim + c0) =
                    make_float2(acc[mi][ni][0], acc[mi][ni][1]);
                *(float2*)(C + (size_t)(r0 + 8) * Ndim + c0) =
                    make_float2(acc[mi][ni][2], acc[mi][ni][3]);
            }
        }
    }
}

// ---------------- weight prep: round to tf32 (+ concats) ----------------
__global__ void round_copy(float* __restrict__ dst, const float* __restrict__ src, int n) {
    int idx = blockIdx.x * 256 + threadIdx.x;
    if (idx < n) dst[idx] = roundtf(src[idx]);
}
__global__ void round_concat_big(const float* __restrict__ ipw, const float* __restrict__ qw,
                                 const float* __restrict__ kw, const float* __restrict__ vw) {
    int idx = blockIdx.x * 256 + threadIdx.x;
    if (idx >= FUSN * Hc) return;
    int row = idx >> 10, col = idx & 1023;
    float v;
    if (row < 4096)      v = ipw[idx];
    else if (row < 5120) v = qw[(row - 4096) * Hc + col];
    else if (row < 5376) v = kw[(row - 5120) * Hc + col];
    else                 v = vw[(row - 5376) * Hc + col];
    g_wbig[idx] = roundtf(v);
}
__global__ void round_concat_kv(const float* __restrict__ kw, const float* __restrict__ vw) {
    int idx = blockIdx.x * 256 + threadIdx.x;
    if (idx >= KVSLD * Hc) return;
    int row = idx >> 10, col = idx & 1023;
    float v = (row < 256) ? kw[row * Hc + col] : vw[(row - 256) * Hc + col];
    g_wkv[idx] = roundtf(v);
}

// ---------------- RMSNorm (+optional residual); nrm output tf32-rounded ----------------
__global__ void resid_rms(const float* __restrict__ a, const float* __restrict__ r,
                          const float* __restrict__ w, float* __restrict__ res_out,
                          float* __restrict__ nrm_out) {
    int row = blockIdx.x;
    int t   = threadIdx.x;
    const float* ap = a + (size_t)row * Hc;
    const float* rp = r ? r + (size_t)row * Hc : nullptr;
    float v[4];
    float ss = 0.f;
#pragma unroll
    for (int i = 0; i < 4; i++) {
        int c = t + i * 256;
        float x = ap[c] + (rp ? rp[c] : 0.f);
        v[i] = x;
        ss += x * x;
    }
#pragma unroll
    for (int off = 16; off; off >>= 1) ss += __shfl_xor_sync(0xffffffffu, ss, off);
    __shared__ float sred[8];
    __shared__ float sscale;
    if ((t & 31) == 0) sred[t >> 5] = ss;
    __syncthreads();
    if (t == 0) {
        float tot = 0.f;
        for (int i = 0; i < 8; i++) tot += sred[i];
        sscale = rsqrtf(tot * (1.f / Hc) + EPSc);
    }
    __syncthreads();
    float scale = sscale;
    float* ro = res_out ? res_out + (size_t)row * Hc : nullptr;
    float* no = nrm_out + (size_t)row * Hc;
#pragma unroll
    for (int i = 0; i < 4; i++) {
        int c = t + i * 256;
        if (ro) ro[c] = v[i];
        no[c] = roundtf(v[i] * scale * w[c]);
    }
}

// ---------------- causal depthwise conv (K=4) + SiLU ----------------
__global__ void conv_silu(const float* __restrict__ cw, const float* __restrict__ cb) {
    int idx = blockIdx.x * blockDim.x + threadIdx.x;
    if (idx >= Mrows * Ic) return;
    int row = idx / Ic;
    int i   = idx - row * Ic;
    int b   = row / Sc;
    int s   = row - b * Sc;
    float acc = cb[i];
#pragma unroll
    for (int k = 0; k < Kcv; k++) {
        int sp = s + k - (Kcv - 1);
        if (sp >= 0)
            acc += cw[i * Kcv + k] * g_xzq[(size_t)(b * Sc + sp) * FUSN + i];
    }
    float r = acc * sigmoidf_(acc);
    g_xs[idx]  = r;
    g_xst[idx] = roundtf(r);
}

// ---------------- dt bias + softplus ----------------
__global__ void bias_softplus(const float* __restrict__ dtb) {
    int idx = blockIdx.x * blockDim.x + threadIdx.x;
    if (idx >= Mrows * Ic) return;
    int i = idx % Ic;
    float x = g_dt[idx] + dtb[i];
    g_dt[idx] = (x > 20.f) ? x : log1pf(expf(x));
}

// ---------------- selective scan (y output tf32-rounded) ----------------
__global__ void scan_kernel(const float* __restrict__ A_log, const float* __restrict__ Dp) {
    int t  = threadIdx.x;
    int c  = t >> 4;
    int n  = t & 15;
    int gi = blockIdx.x * 16 + c;
    int b  = gi / Ic;
    int i  = gi - b * Ic;
    float An = -expf(A_log[i * Nst + n]);
    float Dv = Dp[i];
    float h  = 0.f;
    for (int s = 0; s < Sc; s++) {
        int row = b * Sc + s;
        float dt = g_dt[(size_t)row * Ic + i];
        float xs = g_xs[(size_t)row * Ic + i];
        float Bn = g_proj[row * PROJW + Rc + n];
        float Cn = g_proj[row * PROJW + Rc + Nst + n];
        h = h * expf(dt * An) + dt * Bn * xs;
        float v = h * Cn;
        v += __shfl_xor_sync(0xffffffffu, v, 8);
        v += __shfl_xor_sync(0xffffffffu, v, 4);
        v += __shfl_xor_sync(0xffffffffu, v, 2);
        v += __shfl_xor_sync(0xffffffffu, v, 1);
        if (n == 0) {
            float z  = g_xzq[(size_t)row * FUSN + Ic + i];
            float yv = (v + Dv * xs) * (z * sigmoidf_(z));
            g_y[(size_t)row * Ic + i] = roundtf(yv);
        }
    }
}

// ---------------- rotary (in-place, strided view) ----------------
__global__ void rotary_kernel(float* __restrict__ p, int ld, int coloff, int nheads) {
    int idx = blockIdx.x * blockDim.x + threadIdx.x;
    int tot = Mrows * nheads * 32;
    if (idx >= tot) return;
    int r    = idx / (nheads * 32);
    int rem  = idx - r * (nheads * 32);
    int head = rem >> 5;
    int j    = rem & 31;
    int s    = r % Sc;
    float inv = expf(-((float)(2 * j) / (float)HDc) * logf(10000.0f));
    float f = (float)s * inv;
    float sn, cs;
    sincosf(f, &sn, &cs);
    float* base = p + (size_t)r * ld + coloff + head * HDc;
    float x1 = base[j], x2 = base[j + 32];
    base[j]      = x1 * cs - x2 * sn;
    base[j + 32] = x2 * cs + x1 * sn;
}

// ---------------- dual-window attention v2: smem key/value tiles ----------------
// grid (Sc/8, NHc, Bc); 8 warps, one query per warp.
__global__ __launch_bounds__(256) void attn2() {
    __shared__ float sc[8][WATT + WSSM];   // 20480 B
    __shared__ float tile[64][65];         // 16640 B (K transposed / V rows)
    __shared__ float qs[8][64];            // 2048 B
    int t    = threadIdx.x;
    int w    = t >> 5;
    int lane = t & 31;
    int q0   = blockIdx.x * 8;
    int h    = blockIdx.y;
    int b    = blockIdx.z;
    int rowb = b * Sc;
    int qi   = q0 + w;
    int hk   = h >> 2;

    const float* qp = g_xzq + (size_t)(rowb + qi) * FUSN + 4096 + h * HDc;
    qs[w][lane]      = qp[lane];
    qs[w][lane + 32] = qp[lane + 32];

    int ka = max(0, qi - (WATT - 1)), na = qi - ka + 1;
    int ks = max(0, qi - (WSSM - 1)), ns = qi - ks + 1;
    int caStart = max(0, q0 - (WATT - 1)) & ~63;
    int csStart = max(0, q0 - (WSSM - 1)) & ~63;

    // ---- QK (att) ----
    for (int c = caStart; c <= q0 + 7; c += 64) {
        __syncthreads();
#pragma unroll
        for (int i = 0; i < 4; i++) {
            int id = t + i * 256;
            int r  = id >> 4;
            int d4 = (id & 15) * 4;
            int key = c + r;
            float4 v = make_float4(0.f, 0.f, 0.f, 0.f);
            if (key < Sc)
                v = *(const float4*)(g_xzq + (size_t)(rowb + key) * FUSN + 5120 + hk * HDc + d4);
            tile[d4][r] = v.x; tile[d4 + 1][r] = v.y;
            tile[d4 + 2][r] = v.z; tile[d4 + 3][r] = v.w;
        }
        __syncthreads();
        float a0 = 0.f, a1 = 0.f;
#pragma unroll 8
        for (int d = 0; d < 64; d++) {
            float qd = qs[w][d];
            a0 = fmaf(qd, tile[d][lane], a0);
            a1 = fmaf(qd, tile[d][lane + 32], a1);
        }
        int k0 = c + lane, k1 = c + lane + 32;
        if (k0 >= ka && k0 <= qi) sc[w][k0 - ka] = a0 * 0.125f;
        if (k1 >= ka && k1 <= qi) sc[w][k1 - ka] = a1 * 0.125f;
    }
    // ---- QK (ssm) ----
    for (int c = csStart; c <= q0 + 7; c += 64) {
        __syncthreads();
#pragma unroll
        for (int i = 0; i < 4; i++) {
            int id = t + i * 256;
            int r  = id >> 4;
            int d4 = (id & 15) * 4;
            int key = c + r;
            float4 v = make_float4(0.f, 0.f, 0.f, 0.f);
            if (key < Sc)
                v = *(const float4*)(g_kvssm + (size_t)(rowb + key) * KVSLD + hk * HDc + d4);
            tile[d4][r] = v.x; tile[d4 + 1][r] = v.y;
            tile[d4 + 2][r] = v.z; tile[d4 + 3][r] = v.w;
        }
        __syncthreads();
        float a0 = 0.f, a1 = 0.f;
#pragma unroll 8
        for (int d = 0; d < 64; d++) {
            float qd = qs[w][d];
            a0 = fmaf(qd, tile[d][lane], a0);
            a1 = fmaf(qd, tile[d][lane + 32], a1);
        }
        int k0 = c + lane, k1 = c + lane + 32;
        if (k0 >= ks && k0 <= qi) sc[w][WATT + k0 - ks] = a0 * 0.125f;
        if (k1 >= ks && k1 <= qi) sc[w][WATT + k1 - ks] = a1 * 0.125f;
    }
    __syncwarp();

    // ---- softmax (warp-local) ----
    float mx = -1e30f;
    for (int j = lane; j < na; j += 32) mx = fmaxf(mx, sc[w][j]);
    for (int j = lane; j < ns; j += 32) mx = fmaxf(mx, sc[w][WATT + j]);
#pragma unroll
    for (int off = 16; off; off >>= 1) mx = fmaxf(mx, __shfl_xor_sync(0xffffffffu, mx, off));
    float sum = 0.f;
    for (int j = lane; j < na; j += 32) { float e = expf(sc[w][j] - mx); sc[w][j] = e; sum += e; }
    for (int j = lane; j < ns; j += 32) { float e = expf(sc[w][WATT + j] - mx); sc[w][WATT + j] = e; sum += e; }
#pragma unroll
    for (int off = 16; off; off >>= 1) sum += __shfl_xor_sync(0xffffffffu, sum, off);
    float invs = 1.f / sum;
    __syncwarp();

    // ---- PV (att) ----
    float o0 = 0.f, o1 = 0.f;
    for (int c = caStart; c <= q0 + 7; c += 64) {
        __syncthreads();
#pragma unroll
        for (int i = 0; i < 4; i++) {
            int id = t + i * 256;
            int r  = id >> 4;
            int d4 = (id & 15) * 4;
            int key = c + r;
            float4 v = make_float4(0.f, 0.f, 0.f, 0.f);
            if (key < Sc)
                v = *(const float4*)(g_xzq + (size_t)(rowb + key) * FUSN + 5376 + hk * HDc + d4);
            tile[r][d4] = v.x; tile[r][d4 + 1] = v.y;
            tile[r][d4 + 2] = v.z; tile[r][d4 + 3] = v.w;
        }
        __syncthreads();
#pragma unroll 4
        for (int j = 0; j < 64; j++) {
            int key = c + j;
            float p = (key >= ka && key <= qi) ? sc[w][key - ka] : 0.f;
            o0 = fmaf(p, tile[j][lane], o0);
            o1 = fmaf(p, tile[j][lane + 32], o1);
        }
    }
    // ---- PV (ssm) ----
    for (int c = csStart; c <= q0 + 7; c += 64) {
        __syncthreads();
#pragma unroll
        for (int i = 0; i < 4; i++) {
            int id = t + i * 256;
            int r  = id >> 4;
            int d4 = (id & 15) * 4;
            int key = c + r;
            float4 v = make_float4(0.f, 0.f, 0.f, 0.f);
            if (key < Sc)
                v = *(const float4*)(g_kvssm + (size_t)(rowb + key) * KVSLD + 256 + hk * HDc + d4);
            tile[r][d4] = v.x; tile[r][d4 + 1] = v.y;
            tile[r][d4 + 2] = v.z; tile[r][d4 + 3] = v.w;
        }
        __syncthreads();
#pragma unroll 4
        for (int j = 0; j < 64; j++) {
            int key = c + j;
            float p = (key >= ks && key <= qi) ? sc[w][WATT + key - ks] : 0.f;
            o0 = fmaf(p, tile[j][lane], o0);
            o1 = fmaf(p, tile[j][lane + 32], o1);
        }
    }

    float* op = g_o + (size_t)(rowb + qi) * NHc * HDc + h * HDc;
    op[lane]      = roundtf(o0 * invs);
    op[lane + 32] = roundtf(o1 * invs);
}

// ---------------- SwiGLU (output tf32-rounded) ----------------
__global__ void swiglu_kernel() {
    int idx = blockIdx.x * blockDim.x + threadIdx.x;
    if (idx >= Mrows * IMc) return;
    int row = idx / IMc;
    int c   = idx - row * IMc;
    float g = g_gv[(size_t)row * (2 * IMc) + c];
    float v = g_gv[(size_t)row * (2 * IMc) + IMc + c];
    g_hm[idx] = roundtf(g * sigmoidf_(g) * v);
}

// ---------------- final residual add ----------------
__global__ void final_add(float* __restrict__ out) {
    int idx = blockIdx.x * blockDim.x + threadIdx.x;
    if (idx >= Mrows * Hc) return;
    out[idx] += g_mlpres[idx];
}

// ---------------- host launcher ----------------
extern "C" void kernel_launch(void* const* d_in, const int* in_sizes, int n_in,
                              void* d_out, int out_size) {
    const float* hidden      = (const float*)d_in[0];
    const float* pre_norm_w  = (const float*)d_in[1];
    const float* in_proj_w   = (const float*)d_in[2];
    const float* conv_w      = (const float*)d_in[3];
    const float* conv_b      = (const float*)d_in[4];
    const float* x_proj_w    = (const float*)d_in[5];
    const float* dt_proj_w   = (const float*)d_in[6];
    const float* dt_proj_b   = (const float*)d_in[7];
    const float* A_log       = (const float*)d_in[8];
    const float* Dp          = (const float*)d_in[9];
    const float* out_proj_w  = (const float*)d_in[10];
    const float* ssm_norm_w  = (const float*)d_in[11];
    const float* q_w         = (const float*)d_in[12];
    const float* k_w         = (const float*)d_in[13];
    const float* v_w         = (const float*)d_in[14];
    const float* o_w         = (const float*)d_in[15];
    const float* mlp_norm_w  = (const float*)d_in[16];
    const float* gate_w      = (const float*)d_in[17];
    const float* down_w      = (const float*)d_in[18];
    float* out = (float*)d_out;

    const int smem128 = (BM * PADS + 128 * PADS) * 2 * 4;  // 73728
    const int smem64  = (BM * PADS + 64 * PADS) * 2 * 4;   // 55296
    cudaFuncSetAttribute(gemm_t<128, false>, cudaFuncAttributeMaxDynamicSharedMemorySize, smem128);
    cudaFuncSetAttribute(gemm_t<128, true>,  cudaFuncAttributeMaxDynamicSharedMemorySize, smem128);
    cudaFuncSetAttribute(gemm_t<64, false>,  cudaFuncAttributeMaxDynamicSharedMemorySize, smem64);

    float *hs, *xzq, *xst, *proj, *dt, *y, *tmp, *ssmres, *ssmst;
    float *kvssm, *o, *mlpres, *x2, *gv, *hm;
    float *wbig, *wxp, *wdt, *wop, *wkv, *wo, *wg, *wd;
    cudaGetSymbolAddress((void**)&hs, g_hs);
    cudaGetSymbolAddress((void**)&xzq, g_xzq);
    cudaGetSymbolAddress((void**)&xst, g_xst);
    cudaGetSymbolAddress((void**)&proj, g_proj);
    cudaGetSymbolAddress((void**)&dt, g_dt);
    cudaGetSymbolAddress((void**)&y, g_y);
    cudaGetSymbolAddress((void**)&tmp, g_tmp);
    cudaGetSymbolAddress((void**)&ssmres, g_ssmres);
    cudaGetSymbolAddress((void**)&ssmst, g_ssmst);
    cudaGetSymbolAddress((void**)&kvssm, g_kvssm);
    cudaGetSymbolAddress((void**)&o, g_o);
    cudaGetSymbolAddress((void**)&mlpres, g_mlpres);
    cudaGetSymbolAddress((void**)&x2, g_x2);
    cudaGetSymbolAddress((void**)&gv, g_gv);
    cudaGetSymbolAddress((void**)&hm, g_hm);
    cudaGetSymbolAddress((void**)&wbig, g_wbig);
    cudaGetSymbolAddress((void**)&wxp, g_wxp);
    cudaGetSymbolAddress((void**)&wdt, g_wdt);
    cudaGetSymbolAddress((void**)&wop, g_wop);
    cudaGetSymbolAddress((void**)&wkv, g_wkv);
    cudaGetSymbolAddress((void**)&wo, g_wo);
    cudaGetSymbolAddress((void**)&wg, g_wg);
    cudaGetSymbolAddress((void**)&wd, g_wd);

    // 0. weight prep (round to tf32 + concats)
    round_concat_big<<<(FUSN * Hc + 255) / 256, 256>>>(in_proj_w, q_w, k_w, v_w);
    round_concat_kv<<<(KVSLD * Hc + 255) / 256, 256>>>(k_w, v_w);
    round_copy<<<(PROJW * Ic + 255) / 256, 256>>>(wxp, x_proj_w, PROJW * Ic);
    round_copy<<<(Ic * Rc + 255) / 256, 256>>>(wdt, dt_proj_w, Ic * Rc);
    round_copy<<<(Hc * Ic + 255) / 256, 256>>>(wop, out_proj_w, Hc * Ic);
    round_copy<<<(Hc * NHc * HDc + 255) / 256, 256>>>(wo, o_w, Hc * NHc * HDc);
    round_copy<<<(2 * IMc * Hc + 255) / 256, 256>>>(wg, gate_w, 2 * IMc * Hc);
    round_copy<<<(Hc * IMc + 255) / 256, 256>>>(wd, down_w, Hc * IMc);

    // 1. pre-norm (hs rounded)
    resid_rms<<<Mrows, 256>>>(hidden, nullptr, pre_norm_w, nullptr, hs);
    // 2. fused xz|q|k|v: (2048 x 5632, K=1024)
    gemm_t<128, false><<<dim3(FUSN / 128, Mrows / BM), 256, smem128>>>(hs, wbig, xzq, FUSN, Hc, Hc, Hc);
    // 3. conv + silu (xs full + xst rounded)
    conv_silu<<<(Mrows * Ic) / 256, 256>>>(conv_w, conv_b);
    // 4. x_proj: (2048 x 96, K=2048)
    gemm_t<64, false><<<dim3(2, Mrows / BM), 256, smem64>>>(xst, wxp, proj, PROJW, Ic, Ic, Ic);
    // 5. dt = proj[:, :64] @ dt_w^T  (2048 x 2048, K=64; A raw -> CVTA)
    gemm_t<128, true><<<dim3(Ic / 128, Mrows / BM), 256, smem128>>>(proj, wdt, dt, Ic, Rc, PROJW, Rc);
    bias_softplus<<<(Mrows * Ic) / 256, 256>>>(dt_proj_b);
    // 6. selective scan
    scan_kernel<<<(Bc * Ic) / 16, 256>>>(A_log, Dp);
    // 7. out_proj (2048 x 1024, K=2048); residual + norm
    gemm_t<64, false><<<dim3(Hc / 64, Mrows / BM), 256, smem64>>>(y, wop, tmp, Hc, Ic, Ic, Ic);
    resid_rms<<<Mrows, 256>>>(tmp, hidden, ssm_norm_w, ssmres, ssmst);
    // 8. kv_ssm (2048 x 512, K=1024)
    gemm_t<64, false><<<dim3(KVSLD / 64, Mrows / BM), 256, smem64>>>(ssmst, wkv, kvssm, KVSLD, Hc, Hc, Hc);
    // 9. rotary (q, k_att inside xzq; k_ssm inside kvssm)
    rotary_kernel<<<(Mrows * NHc * 32) / 256, 256>>>(xzq, FUSN, 4096, NHc);
    rotary_kernel<<<(Mrows * NKVc * 32) / 256, 256>>>(xzq, FUSN, 5120, NKVc);
    rotary_kernel<<<(Mrows * NKVc * 32) / 256, 256>>>(kvssm, KVSLD, 0, NKVc);
    // 10. attention v2
    attn2<<<dim3(Sc / 8, NHc, Bc), 256>>>();
    // 11. o proj (2048 x 1024, K=1024); residual + norm
    gemm_t<64, false><<<dim3(Hc / 64, Mrows / BM), 256, smem64>>>(o, wo, tmp, Hc, NHc * HDc, NHc * HDc, NHc * HDc);
    resid_rms<<<Mrows, 256>>>(tmp, ssmres, mlp_norm_w, mlpres, x2);
    // 12. MLP
    gemm_t<128, false><<<dim3(2 * IMc / 128, Mrows / BM), 256, smem128>>>(x2, wg, gv, 2 * IMc, Hc, Hc, Hc);
    swiglu_kernel<<<(Mrows * IMc) / 256, 256>>>();
    gemm_t<64, false><<<dim3(Hc / 64, Mrows / BM), 256, smem64>>>(hm, wd, out, Hc, IMc, IMc, IMc);
    final_add<<<(Mrows * Hc) / 256, 256>>>(out);
}